// round 5
// baseline (speedup 1.0000x reference)
#include <cuda_runtime.h>

#define N_ALPHA 0.05f
#define N_BETA  0.95f
#define BC_TOT  128
#define NN      1024
#define HID     20
#define KC      16          // w per chunk
#define KSPLIT  2
#define KHALF   (NN / KSPLIT)          // 512
#define NCHUNK  (KHALF / KC)           // 32
#define RPC     128         // rows per CTA
#define TPB     128         // threads per block (prop)

// scratch: h0..h3, split-K partials, rowsum partials, 1/rowsum
__device__ float g_h[4][BC_TOT * NN * HID];
__device__ float g_part[KSPLIT][BC_TOT * NN * HID];
__device__ float g_rsp[KSPLIT][BC_TOT * NN];
__device__ float g_invrs[BC_TOT * NN];

static __device__ __forceinline__ unsigned long long fma2(unsigned long long a,
                                                          unsigned long long b,
                                                          unsigned long long c) {
    unsigned long long d;
    asm("fma.rn.f32x2 %0, %1, %2, %3;" : "=l"(d) : "l"(a), "l"(b), "l"(c));
    return d;
}
static __device__ __forceinline__ unsigned long long pack2(float x, float y) {
    unsigned long long d;
    asm("mov.b64 %0, {%1, %2};" : "=l"(d) : "f"(x), "f"(y));
    return d;
}
static __device__ __forceinline__ float2 unpack2(unsigned long long v) {
    float2 f;
    asm("mov.b64 {%0, %1}, %2;" : "=f"(f.x), "=f"(f.y) : "l"(v));
    return f;
}
static __device__ __forceinline__ unsigned smem_u32(const void* p) {
    unsigned a;
    asm("{ .reg .u64 t; cvta.to.shared.u64 t, %1; cvt.u32.u64 %0, t; }"
        : "=r"(a) : "l"(p));
    return a;
}
static __device__ __forceinline__ void cp16(unsigned dst, const void* src) {
    asm volatile("cp.async.cg.shared.global [%0], [%1], 16;" :: "r"(dst), "l"(src));
}

// ---------------------------------------------------------------------------
// h0[bc][n][j] = sum_i x[b][i][n][c] * Ws[i][j] + bs[j]
// ---------------------------------------------------------------------------
__global__ void h0_kernel(const float* __restrict__ x,
                          const float* __restrict__ Ws,
                          const float* __restrict__ bs) {
    __shared__ float wsm[32 * HID];
    __shared__ float bsm[HID];
    int tid = threadIdx.x;
    for (int i = tid; i < 32 * HID; i += 256) wsm[i] = Ws[i];
    if (tid < HID) bsm[tid] = bs[tid];
    __syncthreads();

    int r = blockIdx.x * 256 + tid;
    int c = r & 15;
    int n = (r >> 4) & 1023;
    int b = r >> 14;

    unsigned long long acc[10];
    const unsigned long long* bp = (const unsigned long long*)bsm;
#pragma unroll
    for (int j = 0; j < 10; j++) acc[j] = bp[j];

    const float* xp = x + (size_t)b * 32 * 16384 + n * 16 + c;
#pragma unroll
    for (int i = 0; i < 32; i++) {
        float xv = xp[(size_t)i * 16384];
        unsigned long long xv2 = pack2(xv, xv);
        const unsigned long long* wr = (const unsigned long long*)&wsm[i * HID];
#pragma unroll
        for (int j = 0; j < 10; j++) acc[j] = fma2(xv2, wr[j], acc[j]);
    }
    int bc = b * 16 + c;
    float* o = &g_h[0][((size_t)bc * NN + n) * HID];
#pragma unroll
    for (int j = 0; j < 10; j++) {
        float2 f = unpack2(acc[j]);
        o[2 * j] = f.x; o[2 * j + 1] = f.y;
    }
}

// ---------------------------------------------------------------------------
// split-K partial propagation:
//   part[ks][v] = sum_{w in ks-half} adj[v][w] * h_src[w][:]
//   (FIRST also: rsp[ks][v] = sum_w adj[v][w])
// grid (8 rowblk, KSPLIT, 128 bc); block 128; 1 row/thread; cp.async 2-stage.
// ---------------------------------------------------------------------------
template <bool FIRST>
__global__ void __launch_bounds__(TPB, 6)
prop_partial(const float* __restrict__ adj, int src) {
    __shared__ float adj_s[2][RPC][20];   // rows padded 16->20: conflict-free LDS.128
    __shared__ float hs_s[2][KC * HID];

    int tid = threadIdx.x;
    int rowbase = blockIdx.x * RPC;
    int ks = blockIdx.y;
    int bc = blockIdx.z;
    int wbase = ks * KHALF;

    const float* adjbc = adj + ((size_t)bc << 20) + ((size_t)rowbase << 10) + wbase;
    const float* hp = &g_h[src][(size_t)bc * (NN * HID) + (size_t)wbase * HID];

    unsigned long long acc[10] = {0,0,0,0,0,0,0,0,0,0};
    float rs = 0.f;

    // issue chunk 0 into stage 0
#pragma unroll
    for (int p = 0; p < 4; p++) {
        int g = tid + p * TPB;             // 0..511 float4 granules
        int grow = g >> 2, gq = (g & 3) << 2;
        cp16(smem_u32(&adj_s[0][grow][gq]), adjbc + (size_t)grow * NN + gq);
    }
    if (tid < 80) cp16(smem_u32(&hs_s[0][tid * 4]), hp + tid * 4);
    asm volatile("cp.async.commit_group;");

#pragma unroll 1
    for (int i = 0; i < NCHUNK; i++) {
        int st = i & 1;
        __syncthreads();                   // stage st^1 consumed before overwrite
        if (i + 1 < NCHUNK) {
            int nst = st ^ 1;
            const float* asrc = adjbc + (i + 1) * KC;
#pragma unroll
            for (int p = 0; p < 4; p++) {
                int g = tid + p * TPB;
                int grow = g >> 2, gq = (g & 3) << 2;
                cp16(smem_u32(&adj_s[nst][grow][gq]), asrc + (size_t)grow * NN + gq);
            }
            if (tid < 80)
                cp16(smem_u32(&hs_s[nst][tid * 4]), hp + (i + 1) * (KC * HID) + tid * 4);
            asm volatile("cp.async.commit_group;");
            asm volatile("cp.async.wait_group 1;");
        } else {
            asm volatile("cp.async.wait_group 0;");
        }
        __syncthreads();

        float4 a0[4];
        const float4* p0 = (const float4*)&adj_s[st][tid][0];
#pragma unroll
        for (int q = 0; q < 4; q++) a0[q] = p0[q];

        const float* hb = &hs_s[st][0];
#pragma unroll
        for (int w = 0; w < KC; w++) {
            float v0 = ((const float*)a0)[w];
            if (FIRST) rs += v0;
            unsigned long long v02 = pack2(v0, v0);
            const ulonglong2* hw2 = (const ulonglong2*)(hb + w * HID);
            ulonglong2 q0 = hw2[0], q1 = hw2[1], q2 = hw2[2], q3 = hw2[3], q4 = hw2[4];
            acc[0] = fma2(v02, q0.x, acc[0]); acc[1] = fma2(v02, q0.y, acc[1]);
            acc[2] = fma2(v02, q1.x, acc[2]); acc[3] = fma2(v02, q1.y, acc[3]);
            acc[4] = fma2(v02, q2.x, acc[4]); acc[5] = fma2(v02, q2.y, acc[5]);
            acc[6] = fma2(v02, q3.x, acc[6]); acc[7] = fma2(v02, q3.y, acc[7]);
            acc[8] = fma2(v02, q4.x, acc[8]); acc[9] = fma2(v02, q4.y, acc[9]);
        }
    }

    int v = rowbase + tid;
    size_t ridx = (size_t)bc * NN + v;
    if (FIRST) g_rsp[0][0] = g_rsp[0][0];  // no-op placeholder removed below
    if (FIRST) g_rsp[ks][ridx] = rs;

    float* op = &g_part[ks][ridx * HID];
    float res[20];
#pragma unroll
    for (int j = 0; j < 10; j++) {
        float2 f = unpack2(acc[j]);
        res[2 * j] = f.x; res[2 * j + 1] = f.y;
    }
#pragma unroll
    for (int q = 0; q < 5; q++)
        ((float4*)op)[q] = make_float4(res[4 * q], res[4 * q + 1],
                                       res[4 * q + 2], res[4 * q + 3]);
}

// ---------------------------------------------------------------------------
// combine: h_dst[v] = alpha*h0[v] + beta*(part0+part1+h_src[v]) / rowsum[v]
// ---------------------------------------------------------------------------
template <bool FIRST>
__global__ void __launch_bounds__(256)
combine_kernel(int src, int dst) {
    size_t r = (size_t)blockIdx.x * 256 + threadIdx.x;   // 0..131071

    float ir;
    if (FIRST) {
        ir = 1.f / (g_rsp[0][r] + g_rsp[1][r] + 1.f);
        g_invrs[r] = ir;
    } else {
        ir = g_invrs[r];
    }

    const float4* p0 = (const float4*)&g_part[0][r * HID];
    const float4* p1 = (const float4*)&g_part[1][r * HID];
    const float4* hs = (const float4*)&g_h[src][r * HID];
    const float4* h0 = (const float4*)&g_h[0][r * HID];
    float4* od = (float4*)&g_h[dst][r * HID];

#pragma unroll
    for (int q = 0; q < 5; q++) {
        float4 a = p0[q], b = p1[q], s = hs[q], z = h0[q];
        float4 o;
        o.x = N_ALPHA * z.x + N_BETA * (a.x + b.x + s.x) * ir;
        o.y = N_ALPHA * z.y + N_BETA * (a.y + b.y + s.y) * ir;
        o.z = N_ALPHA * z.z + N_BETA * (a.z + b.z + s.z) * ir;
        o.w = N_ALPHA * z.w + N_BETA * (a.w + b.w + s.w) * ir;
        od[q] = o;
    }
}

// ---------------------------------------------------------------------------
// out[bc][n][o] = sum_{p,j} h_p[bc][n][j] * We[(p*20+j)][o] + be[o]
// ---------------------------------------------------------------------------
__global__ void __launch_bounds__(256) end_kernel(const float* __restrict__ We,
                                                  const float* __restrict__ be,
                                                  float* __restrict__ out) {
    __shared__ float wsm[80 * 32];
    __shared__ float bsm[32];
    __shared__ float hsm[256 * HID];
    int tid = threadIdx.x;
    for (int i = tid; i < 80 * 32; i += 256) wsm[i] = We[i];
    if (tid < 32) bsm[tid] = be[tid];

    int r0 = blockIdx.x * 256;

    unsigned long long acc[16];
    const unsigned long long* bp = (const unsigned long long*)bsm;
#pragma unroll
    for (int p = 0; p < 4; p++) {
        __syncthreads();
        const float4* src4 = (const float4*)(&g_h[p][0] + (size_t)r0 * HID);
#pragma unroll
        for (int k = 0; k < 5; k++)
            ((float4*)hsm)[tid + k * 256] = src4[tid + k * 256];
        __syncthreads();
        if (p == 0) {
#pragma unroll
            for (int o = 0; o < 16; o++) acc[o] = bp[o];
        }
        const float* hr = hsm + tid * HID;
#pragma unroll
        for (int j = 0; j < HID; j++) {
            float v = hr[j];
            unsigned long long v2 = pack2(v, v);
            const unsigned long long* wr =
                (const unsigned long long*)&wsm[(p * HID + j) * 32];
#pragma unroll
            for (int o = 0; o < 16; o++) acc[o] = fma2(v2, wr[o], acc[o]);
        }
    }

    float* op = out + ((size_t)r0 + tid) * 32;
#pragma unroll
    for (int o = 0; o < 16; o++) {
        float2 f = unpack2(acc[o]);
        op[2 * o] = f.x; op[2 * o + 1] = f.y;
    }
}

// ---------------------------------------------------------------------------
extern "C" void kernel_launch(void* const* d_in, const int* in_sizes, int n_in,
                              void* d_out, int out_size) {
    const float* x   = (const float*)d_in[0];
    const float* adj = (const float*)d_in[1];
    const float* Ws  = (const float*)d_in[2];
    const float* bs  = (const float*)d_in[3];
    const float* We  = (const float*)d_in[4];
    const float* be  = (const float*)d_in[5];
    float* out = (float*)d_out;

    dim3 pgrid(NN / RPC, KSPLIT, BC_TOT);   // (8, 2, 128)

    h0_kernel<<<512, 256>>>(x, Ws, bs);
    prop_partial<true ><<<pgrid, TPB>>>(adj, 0);
    combine_kernel<true ><<<512, 256>>>(0, 1);
    prop_partial<false><<<pgrid, TPB>>>(adj, 1);
    combine_kernel<false><<<512, 256>>>(1, 2);
    prop_partial<false><<<pgrid, TPB>>>(adj, 2);
    combine_kernel<false><<<512, 256>>>(2, 3);
    end_kernel<<<512, 256>>>(We, be, out);
}

// round 6
// speedup vs baseline: 1.3427x; 1.3427x over previous
#include <cuda_runtime.h>

#define N_ALPHA 0.05f
#define N_BETA  0.95f
#define BC_TOT  128
#define NN      1024
#define HID     20
#define KC      16
#define KSPLIT  2
#define KHALF   (NN / KSPLIT)          // 512
#define NCHUNK  (KHALF / KC)           // 32
#define RPC     256                    // rows per CTA (2 per thread)
#define TPB     128

// scratch: h0..h3, split-K partials, rowsum partials, 1/rowsum
__device__ float g_h[4][BC_TOT * NN * HID];
__device__ float g_part[KSPLIT][BC_TOT * NN * HID];
__device__ float g_rsp[KSPLIT][BC_TOT * NN];
__device__ float g_invrs[BC_TOT * NN];

static __device__ __forceinline__ unsigned long long fma2(unsigned long long a,
                                                          unsigned long long b,
                                                          unsigned long long c) {
    unsigned long long d;
    asm("fma.rn.f32x2 %0, %1, %2, %3;" : "=l"(d) : "l"(a), "l"(b), "l"(c));
    return d;
}
static __device__ __forceinline__ unsigned long long pack2(float x, float y) {
    unsigned long long d;
    asm("mov.b64 %0, {%1, %2};" : "=l"(d) : "f"(x), "f"(y));
    return d;
}
static __device__ __forceinline__ float2 unpack2(unsigned long long v) {
    float2 f;
    asm("mov.b64 {%0, %1}, %2;" : "=f"(f.x), "=f"(f.y) : "l"(v));
    return f;
}
static __device__ __forceinline__ unsigned smem_u32(const void* p) {
    unsigned a;
    asm("{ .reg .u64 t; cvta.to.shared.u64 t, %1; cvt.u32.u64 %0, t; }"
        : "=r"(a) : "l"(p));
    return a;
}
static __device__ __forceinline__ void cp16(unsigned dst, const void* src) {
    asm volatile("cp.async.cg.shared.global [%0], [%1], 16;" :: "r"(dst), "l"(src));
}

// ---------------------------------------------------------------------------
// h0[bc][n][j] = sum_i x[b][i][n][c] * Ws[i][j] + bs[j]
// ---------------------------------------------------------------------------
__global__ void h0_kernel(const float* __restrict__ x,
                          const float* __restrict__ Ws,
                          const float* __restrict__ bs) {
    __shared__ float wsm[32 * HID];
    __shared__ float bsm[HID];
    int tid = threadIdx.x;
    for (int i = tid; i < 32 * HID; i += 256) wsm[i] = Ws[i];
    if (tid < HID) bsm[tid] = bs[tid];
    __syncthreads();

    int r = blockIdx.x * 256 + tid;
    int c = r & 15;
    int n = (r >> 4) & 1023;
    int b = r >> 14;

    unsigned long long acc[10];
    const unsigned long long* bp = (const unsigned long long*)bsm;
#pragma unroll
    for (int j = 0; j < 10; j++) acc[j] = bp[j];

    const float* xp = x + (size_t)b * 32 * 16384 + n * 16 + c;
#pragma unroll
    for (int i = 0; i < 32; i++) {
        float xv = xp[(size_t)i * 16384];
        unsigned long long xv2 = pack2(xv, xv);
        const unsigned long long* wr = (const unsigned long long*)&wsm[i * HID];
#pragma unroll
        for (int j = 0; j < 10; j++) acc[j] = fma2(xv2, wr[j], acc[j]);
    }
    int bc = b * 16 + c;
    float* o = &g_h[0][((size_t)bc * NN + n) * HID];
#pragma unroll
    for (int j = 0; j < 10; j++) {
        float2 f = unpack2(acc[j]);
        o[2 * j] = f.x; o[2 * j + 1] = f.y;
    }
}

// ---------------------------------------------------------------------------
// split-K partial propagation:
//   part[ks][v][:] = sum_{w in half ks} adj[v][w] * h_src[w][:]
//   FIRST also: rsp[ks][v] = sum_{w in half} adj[v][w]
// grid (4, KSPLIT, 128); block 128; 2 rows/thread; cp.async double-buffered.
// smem adj rows padded 16->20 floats: LDS.128 at 80B stride = conflict-free.
// ---------------------------------------------------------------------------
template <bool FIRST>
__global__ void __launch_bounds__(TPB, 4)
prop_partial(const float* __restrict__ adj, int src) {
    __shared__ float adj_s[2][RPC][20];
    __shared__ float hs_s[2][KC * HID];

    int tid = threadIdx.x;
    int rowbase = blockIdx.x * RPC;
    int ks = blockIdx.y;
    int bc = blockIdx.z;
    int wbase = ks * KHALF;

    const float* adjbc = adj + ((size_t)bc << 20) + ((size_t)rowbase << 10) + wbase;
    const float* hp = &g_h[src][(size_t)bc * (NN * HID) + (size_t)wbase * HID];

    int grow[8], gq[8];
#pragma unroll
    for (int p = 0; p < 8; p++) {
        int g = tid + p * TPB;             // 0..1023 float4 granules
        grow[p] = g >> 2;
        gq[p] = (g & 3) << 2;
    }

    unsigned long long acc0[10] = {0,0,0,0,0,0,0,0,0,0};
    unsigned long long acc1[10] = {0,0,0,0,0,0,0,0,0,0};
    float rs0 = 0.f, rs1 = 0.f;

    // issue chunk 0 into stage 0
#pragma unroll
    for (int p = 0; p < 8; p++)
        cp16(smem_u32(&adj_s[0][grow[p]][gq[p]]),
             adjbc + (size_t)grow[p] * NN + gq[p]);
    if (tid < 80) cp16(smem_u32(&hs_s[0][tid * 4]), hp + tid * 4);
    asm volatile("cp.async.commit_group;");

#pragma unroll 1
    for (int i = 0; i < NCHUNK; i++) {
        int st = i & 1;
        __syncthreads();                   // stage st^1 consumed before overwrite
        if (i + 1 < NCHUNK) {
            int nst = st ^ 1;
            const float* asrc = adjbc + (i + 1) * KC;
#pragma unroll
            for (int p = 0; p < 8; p++)
                cp16(smem_u32(&adj_s[nst][grow[p]][gq[p]]),
                     asrc + (size_t)grow[p] * NN + gq[p]);
            if (tid < 80)
                cp16(smem_u32(&hs_s[nst][tid * 4]),
                     hp + (i + 1) * (KC * HID) + tid * 4);
            asm volatile("cp.async.commit_group;");
            asm volatile("cp.async.wait_group 1;");
        } else {
            asm volatile("cp.async.wait_group 0;");
        }
        __syncthreads();

        float4 a0[4], a1[4];
        const float4* p0 = (const float4*)&adj_s[st][tid][0];
        const float4* p1 = (const float4*)&adj_s[st][tid + TPB][0];
#pragma unroll
        for (int q = 0; q < 4; q++) { a0[q] = p0[q]; a1[q] = p1[q]; }

        const float* hb = &hs_s[st][0];
#pragma unroll
        for (int w = 0; w < KC; w++) {
            float v0 = ((const float*)a0)[w];
            float v1 = ((const float*)a1)[w];
            if (FIRST) { rs0 += v0; rs1 += v1; }
            unsigned long long v02 = pack2(v0, v0);
            unsigned long long v12 = pack2(v1, v1);
            const ulonglong2* hw2 = (const ulonglong2*)(hb + w * HID);
            ulonglong2 q0 = hw2[0], q1 = hw2[1], q2 = hw2[2], q3 = hw2[3], q4 = hw2[4];
            unsigned long long hv[10] = {q0.x, q0.y, q1.x, q1.y, q2.x,
                                         q2.y, q3.x, q3.y, q4.x, q4.y};
#pragma unroll
            for (int j = 0; j < 10; j++) {
                acc0[j] = fma2(v02, hv[j], acc0[j]);
                acc1[j] = fma2(v12, hv[j], acc1[j]);
            }
        }
    }

    int v0 = rowbase + tid;
    int v1 = v0 + TPB;
    size_t r0 = (size_t)bc * NN + v0;
    size_t r1 = (size_t)bc * NN + v1;
    if (FIRST) {
        g_rsp[ks][r0] = rs0;
        g_rsp[ks][r1] = rs1;
    }

#pragma unroll 2
    for (int rr = 0; rr < 2; rr++) {
        const unsigned long long* acc = rr ? acc1 : acc0;
        float* op = &g_part[ks][(rr ? r1 : r0) * HID];
        float res[20];
#pragma unroll
        for (int j = 0; j < 10; j++) {
            float2 f = unpack2(acc[j]);
            res[2 * j] = f.x; res[2 * j + 1] = f.y;
        }
#pragma unroll
        for (int q = 0; q < 5; q++)
            ((float4*)op)[q] = make_float4(res[4 * q], res[4 * q + 1],
                                           res[4 * q + 2], res[4 * q + 3]);
    }
}

// ---------------------------------------------------------------------------
// combine: h_dst[v] = alpha*h0[v] + beta*(part0+part1+h_src[v]) / rowsum[v]
// ---------------------------------------------------------------------------
template <bool FIRST>
__global__ void __launch_bounds__(256)
combine_kernel(int src, int dst) {
    size_t r = (size_t)blockIdx.x * 256 + threadIdx.x;

    float ir;
    if (FIRST) {
        ir = 1.f / (g_rsp[0][r] + g_rsp[1][r] + 1.f);
        g_invrs[r] = ir;
    } else {
        ir = g_invrs[r];
    }

    const float4* p0 = (const float4*)&g_part[0][r * HID];
    const float4* p1 = (const float4*)&g_part[1][r * HID];
    const float4* hs = (const float4*)&g_h[src][r * HID];
    const float4* h0 = (const float4*)&g_h[0][r * HID];
    float4* od = (float4*)&g_h[dst][r * HID];

#pragma unroll
    for (int q = 0; q < 5; q++) {
        float4 a = p0[q], b = p1[q], s = hs[q], z = h0[q];
        float4 o;
        o.x = N_ALPHA * z.x + N_BETA * (a.x + b.x + s.x) * ir;
        o.y = N_ALPHA * z.y + N_BETA * (a.y + b.y + s.y) * ir;
        o.z = N_ALPHA * z.z + N_BETA * (a.z + b.z + s.z) * ir;
        o.w = N_ALPHA * z.w + N_BETA * (a.w + b.w + s.w) * ir;
        od[q] = o;
    }
}

// ---------------------------------------------------------------------------
// out[bc][n][o] = sum_{p,j} h_p[bc][n][j] * We[(p*20+j)][o] + be[o]
// ---------------------------------------------------------------------------
__global__ void __launch_bounds__(256) end_kernel(const float* __restrict__ We,
                                                  const float* __restrict__ be,
                                                  float* __restrict__ out) {
    __shared__ float wsm[80 * 32];
    __shared__ float bsm[32];
    __shared__ float hsm[256 * HID];
    int tid = threadIdx.x;
    for (int i = tid; i < 80 * 32; i += 256) wsm[i] = We[i];
    if (tid < 32) bsm[tid] = be[tid];

    int r0 = blockIdx.x * 256;

    unsigned long long acc[16];
    const unsigned long long* bp = (const unsigned long long*)bsm;
#pragma unroll
    for (int p = 0; p < 4; p++) {
        __syncthreads();
        const float4* src4 = (const float4*)(&g_h[p][0] + (size_t)r0 * HID);
#pragma unroll
        for (int k = 0; k < 5; k++)
            ((float4*)hsm)[tid + k * 256] = src4[tid + k * 256];
        __syncthreads();
        if (p == 0) {
#pragma unroll
            for (int o = 0; o < 16; o++) acc[o] = bp[o];
        }
        const float* hr = hsm + tid * HID;
#pragma unroll
        for (int j = 0; j < HID; j++) {
            float v = hr[j];
            unsigned long long v2 = pack2(v, v);
            const unsigned long long* wr =
                (const unsigned long long*)&wsm[(p * HID + j) * 32];
#pragma unroll
            for (int o = 0; o < 16; o++) acc[o] = fma2(v2, wr[o], acc[o]);
        }
    }

    float* op = out + ((size_t)r0 + tid) * 32;
#pragma unroll
    for (int o = 0; o < 16; o++) {
        float2 f = unpack2(acc[o]);
        op[2 * o] = f.x; op[2 * o + 1] = f.y;
    }
}

// ---------------------------------------------------------------------------
extern "C" void kernel_launch(void* const* d_in, const int* in_sizes, int n_in,
                              void* d_out, int out_size) {
    const float* x   = (const float*)d_in[0];
    const float* adj = (const float*)d_in[1];
    const float* Ws  = (const float*)d_in[2];
    const float* bs  = (const float*)d_in[3];
    const float* We  = (const float*)d_in[4];
    const float* be  = (const float*)d_in[5];
    float* out = (float*)d_out;

    dim3 pgrid(NN / RPC, KSPLIT, BC_TOT);   // (4, 2, 128) = 1024 CTAs

    h0_kernel<<<512, 256>>>(x, Ws, bs);
    prop_partial<true ><<<pgrid, TPB>>>(adj, 0);
    combine_kernel<true ><<<512, 256>>>(0, 1);
    prop_partial<false><<<pgrid, TPB>>>(adj, 1);
    combine_kernel<false><<<512, 256>>>(1, 2);
    prop_partial<false><<<pgrid, TPB>>>(adj, 2);
    combine_kernel<false><<<512, 256>>>(2, 3);
    end_kernel<<<512, 256>>>(We, be, out);
}

// round 8
// speedup vs baseline: 1.7513x; 1.3043x over previous
#include <cuda_runtime.h>
#include <cuda_bf16.h>
#include <cstdint>

#define N_ALPHA 0.05f
#define N_BETA  0.95f
#define BC_TOT  128
#define NN      1024
#define HID     20
#define KCH     32            // K per chunk
#define NCHUNK  (NN / KCH)    // 32
#define TM      128           // rows per CTA

// A tile: 128 rows x 32 bf16, rows padded to 80B (40 bf16) -> conflict-free ldmatrix
#define A_T     (128 * 80)    // 10240 B
#define B_T     (32 * 80)     // 2560 B
#define STAGE   (2 * A_T + 2 * B_T)   // 25600
#define OFF_AH  0
#define OFF_AL  A_T
#define OFF_BH  (2 * A_T)
#define OFF_BL  (2 * A_T + B_T)
#define SMEM_SZ (2 * STAGE)   // 51200

// scratch: h0..h3
__device__ float g_h[4][BC_TOT * NN * HID];

static __device__ __forceinline__ unsigned smem_u32(const void* p) {
    unsigned a;
    asm("{ .reg .u64 t; cvta.to.shared.u64 t, %1; cvt.u32.u64 %0, t; }"
        : "=r"(a) : "l"(p));
    return a;
}
static __device__ __forceinline__ unsigned long long fma2(unsigned long long a,
                                                          unsigned long long b,
                                                          unsigned long long c) {
    unsigned long long d;
    asm("fma.rn.f32x2 %0, %1, %2, %3;" : "=l"(d) : "l"(a), "l"(b), "l"(c));
    return d;
}
static __device__ __forceinline__ unsigned long long pack2(float x, float y) {
    unsigned long long d;
    asm("mov.b64 %0, {%1, %2};" : "=l"(d) : "f"(x), "f"(y));
    return d;
}
static __device__ __forceinline__ float2 unpack2(unsigned long long v) {
    float2 f;
    asm("mov.b64 {%0, %1}, %2;" : "=f"(f.x), "=f"(f.y) : "l"(v));
    return f;
}
static __device__ __forceinline__ void ldm_x4(uint32_t* r, uint32_t addr) {
    asm volatile("ldmatrix.sync.aligned.m8n8.x4.shared.b16 {%0,%1,%2,%3}, [%4];"
                 : "=r"(r[0]), "=r"(r[1]), "=r"(r[2]), "=r"(r[3]) : "r"(addr));
}
static __device__ __forceinline__ void ldm_x2t(uint32_t* r, uint32_t addr) {
    asm volatile("ldmatrix.sync.aligned.m8n8.x2.trans.shared.b16 {%0,%1}, [%2];"
                 : "=r"(r[0]), "=r"(r[1]) : "r"(addr));
}
static __device__ __forceinline__ void mma_bf16(float* c, const uint32_t* a,
                                                const uint32_t* b) {
    asm volatile(
        "mma.sync.aligned.m16n8k16.row.col.f32.bf16.bf16.f32 "
        "{%0,%1,%2,%3}, {%4,%5,%6,%7}, {%8,%9}, {%0,%1,%2,%3};"
        : "+f"(c[0]), "+f"(c[1]), "+f"(c[2]), "+f"(c[3])
        : "r"(a[0]), "r"(a[1]), "r"(a[2]), "r"(a[3]), "r"(b[0]), "r"(b[1]));
}

// ---------------------------------------------------------------------------
// h0[bc][n][j] = sum_i x[b][i][n][c] * Ws[i][j] + bs[j]
// ---------------------------------------------------------------------------
__global__ void h0_kernel(const float* __restrict__ x,
                          const float* __restrict__ Ws,
                          const float* __restrict__ bs) {
    __shared__ float wsm[32 * HID];
    __shared__ float bsm[HID];
    int tid = threadIdx.x;
    for (int i = tid; i < 32 * HID; i += 256) wsm[i] = Ws[i];
    if (tid < HID) bsm[tid] = bs[tid];
    __syncthreads();

    int r = blockIdx.x * 256 + tid;
    int c = r & 15;
    int n = (r >> 4) & 1023;
    int b = r >> 14;

    unsigned long long acc[10];
    const unsigned long long* bp = (const unsigned long long*)bsm;
#pragma unroll
    for (int j = 0; j < 10; j++) acc[j] = bp[j];

    const float* xp = x + (size_t)b * 32 * 16384 + n * 16 + c;
#pragma unroll
    for (int i = 0; i < 32; i++) {
        float xv = xp[(size_t)i * 16384];
        unsigned long long xv2 = pack2(xv, xv);
        const unsigned long long* wr = (const unsigned long long*)&wsm[i * HID];
#pragma unroll
        for (int j = 0; j < 10; j++) acc[j] = fma2(xv2, wr[j], acc[j]);
    }
    int bc = b * 16 + c;
    float* o = &g_h[0][((size_t)bc * NN + n) * HID];
#pragma unroll
    for (int j = 0; j < 10; j++) {
        float2 f = unpack2(acc[j]);
        o[2 * j] = f.x; o[2 * j + 1] = f.y;
    }
}

// ---------------------------------------------------------------------------
// propagation via mma.sync (bf16 hi/lo emulated fp32):
//   D[v][n<20] = sum_w adj[v][w] h[w][n] ; D[v][20] = rowsum (ones col in Bhi)
//   h_dst[v] = alpha*h0[v] + beta*(D[v][:20] + h_src[v]) / (D[v][20] + 1)
// grid (8, 128), block 256 (8 warps x m16), double-buffered smem, 80B rows.
// ---------------------------------------------------------------------------
__global__ void __launch_bounds__(256, 3)
prop_mma(const float* __restrict__ adj, int src, int dst) {
    extern __shared__ char smem[];
    const uint32_t sb = smem_u32(smem);
    int tid = threadIdx.x;
    int lane = tid & 31, wid = tid >> 5;
    int rowbase = blockIdx.x * TM;
    int bc = blockIdx.y;

    const float* A = adj + ((size_t)bc << 20) + ((size_t)rowbase << 10);
    const float* H = &g_h[src][(size_t)bc * (NN * HID)];

    // zero B regions (pad cols 21..39 stay zero forever); ones col n=20 in Bhi
    for (int st = 0; st < 2; st++) {
        uint32_t* bb = (uint32_t*)(smem + st * STAGE + OFF_BH);
        for (int i = tid; i < (2 * B_T) / 4; i += 256) bb[i] = 0;
    }
    __syncthreads();
    if (tid < 32) {
        *(uint16_t*)(smem + 0 * STAGE + OFF_BH + tid * 80 + 40) = 0x3F80;
        *(uint16_t*)(smem + 1 * STAGE + OFF_BH + tid * 80 + 40) = 0x3F80;
    }

    // per-thread A granules: g = tid + p*256 -> row g>>3, col (g&7)*4
    int arow[4], acol[4];
#pragma unroll
    for (int p = 0; p < 4; p++) {
        int g = tid + p * 256;
        arow[p] = g >> 3;
        acol[p] = (g & 7) * 4;
    }
    bool hasb = tid < 160;
    int bk = tid / 5, bc4 = (tid % 5) * 4;

    float acc[3][4];
#pragma unroll
    for (int nt = 0; nt < 3; nt++)
#pragma unroll
        for (int q = 0; q < 4; q++) acc[nt][q] = 0.f;

    // prefetch chunk 0
    float4 abuf[4], bbuf;
#pragma unroll
    for (int p = 0; p < 4; p++)
        abuf[p] = __ldcs((const float4*)(A + (size_t)arow[p] * NN + acol[p]));
    if (hasb) bbuf = *(const float4*)(H + (size_t)bk * HID + bc4);

#pragma unroll 1
    for (int i = 0; i < NCHUNK; i++) {
        int st = i & 1;
        uint32_t stb = sb + st * STAGE;
        __syncthreads();   // stage st free (its last readers finished iter i-2)

        // ---- split + STS A
#pragma unroll
        for (int p = 0; p < 4; p++) {
            uint32_t u0 = __float_as_uint(abuf[p].x), u1 = __float_as_uint(abuf[p].y);
            uint32_t u2 = __float_as_uint(abuf[p].z), u3 = __float_as_uint(abuf[p].w);
            uint32_t hp0, hp1;
            asm("prmt.b32 %0, %1, %2, 0x7632;" : "=r"(hp0) : "r"(u0), "r"(u1));
            asm("prmt.b32 %0, %1, %2, 0x7632;" : "=r"(hp1) : "r"(u2), "r"(u3));
            float l0 = abuf[p].x - __uint_as_float(u0 & 0xFFFF0000u);
            float l1 = abuf[p].y - __uint_as_float(u1 & 0xFFFF0000u);
            float l2 = abuf[p].z - __uint_as_float(u2 & 0xFFFF0000u);
            float l3 = abuf[p].w - __uint_as_float(u3 & 0xFFFF0000u);
            uint32_t lp0, lp1;
            asm("cvt.rn.bf16x2.f32 %0, %1, %2;" : "=r"(lp0) : "f"(l1), "f"(l0));
            asm("cvt.rn.bf16x2.f32 %0, %1, %2;" : "=r"(lp1) : "f"(l3), "f"(l2));
            uint32_t off = (uint32_t)arow[p] * 80 + (uint32_t)acol[p] * 2;
            *(uint2*)(smem + st * STAGE + OFF_AH + off) = make_uint2(hp0, hp1);
            *(uint2*)(smem + st * STAGE + OFF_AL + off) = make_uint2(lp0, lp1);
        }
        // ---- split + STS B
        if (hasb) {
            uint32_t u0 = __float_as_uint(bbuf.x), u1 = __float_as_uint(bbuf.y);
            uint32_t u2 = __float_as_uint(bbuf.z), u3 = __float_as_uint(bbuf.w);
            uint32_t hp0, hp1;
            asm("prmt.b32 %0, %1, %2, 0x7632;" : "=r"(hp0) : "r"(u0), "r"(u1));
            asm("prmt.b32 %0, %1, %2, 0x7632;" : "=r"(hp1) : "r"(u2), "r"(u3));
            float l0 = bbuf.x - __uint_as_float(u0 & 0xFFFF0000u);
            float l1 = bbuf.y - __uint_as_float(u1 & 0xFFFF0000u);
            float l2 = bbuf.z - __uint_as_float(u2 & 0xFFFF0000u);
            float l3 = bbuf.w - __uint_as_float(u3 & 0xFFFF0000u);
            uint32_t lp0, lp1;
            asm("cvt.rn.bf16x2.f32 %0, %1, %2;" : "=r"(lp0) : "f"(l1), "f"(l0));
            asm("cvt.rn.bf16x2.f32 %0, %1, %2;" : "=r"(lp1) : "f"(l3), "f"(l2));
            uint32_t off = (uint32_t)bk * 80 + (uint32_t)bc4 * 2;
            *(uint2*)(smem + st * STAGE + OFF_BH + off) = make_uint2(hp0, hp1);
            *(uint2*)(smem + st * STAGE + OFF_BL + off) = make_uint2(lp0, lp1);
        }

        // ---- prefetch chunk i+1 into regs (latency hidden behind mma below)
        if (i + 1 < NCHUNK) {
            const float* ap = A + (i + 1) * KCH;
#pragma unroll
            for (int p = 0; p < 4; p++)
                abuf[p] = __ldcs((const float4*)(ap + (size_t)arow[p] * NN + acol[p]));
            if (hasb)
                bbuf = *(const float4*)(H + (size_t)((i + 1) * KCH + bk) * HID + bc4);
        }
        __syncthreads();   // stage st fully written

        // ---- ldmatrix + mma: warp owns rows [wid*16, wid*16+16)
#pragma unroll
        for (int s = 0; s < 2; s++) {
            uint32_t ah[4], al[4];
            uint32_t aaddr = stb + OFF_AH +
                             (uint32_t)(wid * 16 + (lane & 15)) * 80 +
                             (uint32_t)(s * 32 + ((lane >> 4) << 4));
            ldm_x4(ah, aaddr);
            ldm_x4(al, aaddr + A_T);
            uint32_t brow = stb + OFF_BH + (uint32_t)(s * 16 + (lane & 15)) * 80;
#pragma unroll
            for (int nt = 0; nt < 3; nt++) {
                uint32_t bh[2], bl[2];
                ldm_x2t(bh, brow + nt * 16);
                ldm_x2t(bl, brow + nt * 16 + B_T);
                mma_bf16(acc[nt], ah, bh);
                mma_bf16(acc[nt], ah, bl);
                mma_bf16(acc[nt], al, bh);
            }
        }
    }

    // ---- epilogue: D frags -> smem (rows padded to 112B), then combine
    __syncthreads();
    {
        char* darea = smem + wid * (16 * 112);
        int r0 = lane >> 2;
        int cb = (lane & 3) * 2;
#pragma unroll
        for (int nt = 0; nt < 3; nt++) {
            int cbyte = (nt * 8 + cb) * 4;
            *(float2*)(darea + r0 * 112 + cbyte) = make_float2(acc[nt][0], acc[nt][1]);
            *(float2*)(darea + (r0 + 8) * 112 + cbyte) = make_float2(acc[nt][2], acc[nt][3]);
        }
    }
    __syncthreads();
    if (tid < TM) {
        const float* Drow = (const float*)(smem + (tid >> 4) * (16 * 112) +
                                           (tid & 15) * 112);
        int v = rowbase + tid;
        float ir = 1.f / (Drow[20] + 1.f);
        const float* hsr = H + (size_t)v * HID;
        const float* h0r = &g_h[0][(size_t)bc * (NN * HID) + (size_t)v * HID];
        float* outr = &g_h[dst][(size_t)bc * (NN * HID) + (size_t)v * HID];
        float res[20];
#pragma unroll
        for (int j = 0; j < 20; j++)
            res[j] = N_ALPHA * h0r[j] + N_BETA * (Drow[j] + hsr[j]) * ir;
#pragma unroll
        for (int q = 0; q < 5; q++)
            ((float4*)outr)[q] = make_float4(res[4 * q], res[4 * q + 1],
                                             res[4 * q + 2], res[4 * q + 3]);
    }
}

// ---------------------------------------------------------------------------
// out[bc][n][o] = sum_{p,j} h_p[bc][n][j] * We[(p*20+j)][o] + be[o]
// ---------------------------------------------------------------------------
__global__ void __launch_bounds__(256) end_kernel(const float* __restrict__ We,
                                                  const float* __restrict__ be,
                                                  float* __restrict__ out) {
    __shared__ float wsm[80 * 32];
    __shared__ float bsm[32];
    __shared__ float hsm[256 * HID];
    int tid = threadIdx.x;
    for (int i = tid; i < 80 * 32; i += 256) wsm[i] = We[i];
    if (tid < 32) bsm[tid] = be[tid];

    int r0 = blockIdx.x * 256;

    unsigned long long acc[16];
    const unsigned long long* bp = (const unsigned long long*)bsm;
#pragma unroll
    for (int p = 0; p < 4; p++) {
        __syncthreads();
        const float4* src4 = (const float4*)(&g_h[p][0] + (size_t)r0 * HID);
#pragma unroll
        for (int k = 0; k < 5; k++)
            ((float4*)hsm)[tid + k * 256] = src4[tid + k * 256];
        __syncthreads();
        if (p == 0) {
#pragma unroll
            for (int o = 0; o < 16; o++) acc[o] = bp[o];
        }
        const float* hr = hsm + tid * HID;
#pragma unroll
        for (int j = 0; j < HID; j++) {
            float v = hr[j];
            unsigned long long v2 = pack2(v, v);
            const unsigned long long* wr =
                (const unsigned long long*)&wsm[(p * HID + j) * 32];
#pragma unroll
            for (int o = 0; o < 16; o++) acc[o] = fma2(v2, wr[o], acc[o]);
        }
    }

    float* op = out + ((size_t)r0 + tid) * 32;
#pragma unroll
    for (int o = 0; o < 16; o++) {
        float2 f = unpack2(acc[o]);
        op[2 * o] = f.x; op[2 * o + 1] = f.y;
    }
}

// ---------------------------------------------------------------------------
extern "C" void kernel_launch(void* const* d_in, const int* in_sizes, int n_in,
                              void* d_out, int out_size) {
    const float* x   = (const float*)d_in[0];
    const float* adj = (const float*)d_in[1];
    const float* Ws  = (const float*)d_in[2];
    const float* bs  = (const float*)d_in[3];
    const float* We  = (const float*)d_in[4];
    const float* be  = (const float*)d_in[5];
    float* out = (float*)d_out;

    cudaFuncSetAttribute(prop_mma, cudaFuncAttributeMaxDynamicSharedMemorySize,
                         SMEM_SZ);

    dim3 pgrid(NN / TM, BC_TOT);   // (8, 128)

    h0_kernel<<<512, 256>>>(x, Ws, bs);
    prop_mma<<<pgrid, 256, SMEM_SZ>>>(adj, 0, 1);
    prop_mma<<<pgrid, 256, SMEM_SZ>>>(adj, 1, 2);
    prop_mma<<<pgrid, 256, SMEM_SZ>>>(adj, 2, 3);
    end_kernel<<<512, 256>>>(We, be, out);
}